// round 1
// baseline (speedup 1.0000x reference)
#include <cuda_runtime.h>

// Problem constants
#define T_  4
#define B_  4
#define N_  1024
#define D_  512
#define H_  8
#define HD_ 64
#define M_  (T_*B_*N_)   // 16384 rows

// Scratch (no cudaMalloc allowed): q, k, v, ctx — 33.5 MB each
__device__ float g_q  [(size_t)M_*D_];
__device__ float g_k  [(size_t)M_*D_];
__device__ float g_v  [(size_t)M_*D_];
__device__ float g_ctx[(size_t)M_*D_];

// ---------------------------------------------------------------------------
// C[M,Nc] = A[M,K] @ W[Nc,K]^T + bias   (torch Linear semantics)
// 64x64 tile, BK=32, 256 threads, 4x4 per thread.
// ---------------------------------------------------------------------------
__global__ __launch_bounds__(256) void gemm_bias_kernel(
    const float* __restrict__ A, const float* __restrict__ W,
    const float* __restrict__ bias, float* __restrict__ C,
    int M, int Nc, int K)
{
    __shared__ float As[64][33];
    __shared__ float Ws[64][33];

    const int tid = threadIdx.x;
    const int ty  = tid >> 4, tx = tid & 15;
    const int r0  = ty * 4,  c0 = tx * 4;
    const int mb  = blockIdx.y * 64, nb = blockIdx.x * 64;

    float acc[4][4] = {};

    for (int kb = 0; kb < K; kb += 32) {
        #pragma unroll
        for (int l = tid; l < 64*32; l += 256) {
            int m = l >> 5, kk = l & 31;
            As[m][kk] = A[(size_t)(mb + m) * K + kb + kk];
        }
        #pragma unroll
        for (int l = tid; l < 64*32; l += 256) {
            int c = l >> 5, kk = l & 31;
            Ws[c][kk] = W[(size_t)(nb + c) * K + kb + kk];
        }
        __syncthreads();

        #pragma unroll 8
        for (int kk = 0; kk < 32; kk++) {
            float a[4], b[4];
            #pragma unroll
            for (int i = 0; i < 4; i++) a[i] = As[r0 + i][kk];
            #pragma unroll
            for (int j = 0; j < 4; j++) b[j] = Ws[c0 + j][kk];
            #pragma unroll
            for (int i = 0; i < 4; i++)
                #pragma unroll
                for (int j = 0; j < 4; j++)
                    acc[i][j] = fmaf(a[i], b[j], acc[i][j]);
        }
        __syncthreads();
    }

    #pragma unroll
    for (int i = 0; i < 4; i++) {
        #pragma unroll
        for (int j = 0; j < 4; j++) {
            C[(size_t)(mb + r0 + i) * Nc + nb + c0 + j] =
                acc[i][j] + bias[nb + c0 + j];
        }
    }
}

// ---------------------------------------------------------------------------
// ReLU-normalized attention, streamed over key tiles (no 1024x1024 matrix).
// Block: 64 queries of one (t,b,h). Loop over 32-key tiles:
//   S = (Q K^T) * 0.125 ; P = relu(S) ; denom += rowsum(P) ; acc += P V
// Epilogue: ctx = acc / (denom + eps), written in (t,b,n,D) layout.
// ---------------------------------------------------------------------------
__global__ __launch_bounds__(256) void attn_kernel(
    const float* __restrict__ q, const float* __restrict__ k,
    const float* __restrict__ v, float* __restrict__ ctx)
{
    __shared__ float Qs [64][65];   // [query][hd]
    __shared__ float Kts[64][33];   // [hd][key]   (transposed on load)
    __shared__ float Vs [32][65];   // [key][hd]
    __shared__ float Ss [64][33];   // [query][key] = relu(scaled scores)
    __shared__ float denom[64];

    const int tid = threadIdx.x;
    const int hi  = blockIdx.y;          // tb*H + h, 0..127
    const int h   = hi & (H_ - 1);
    const int tb  = hi >> 3;
    const size_t base = (size_t)tb * N_ * D_ + (size_t)h * HD_;
    const int q0  = blockIdx.x * 64;

    const int ty = tid >> 4, tx = tid & 15;
    const int r0 = ty * 4;       // query rows (4 per thread)
    const int cS = tx * 2;       // S columns  (2 per thread; 32 keys/tile)
    const int cA = tx * 4;       // acc columns (4 per thread; HD=64)

    for (int l = tid; l < 64*64; l += 256) {
        int r = l >> 6, c = l & 63;
        Qs[r][c] = q[base + (size_t)(q0 + r) * D_ + c];
    }
    if (tid < 64) denom[tid] = 0.f;
    float acc[4][4] = {};
    __syncthreads();

    for (int k0 = 0; k0 < N_; k0 += 32) {
        for (int l = tid; l < 32*64; l += 256) {
            int key = l >> 6, c = l & 63;
            Kts[c][key] = k[base + (size_t)(k0 + key) * D_ + c];
        }
        for (int l = tid; l < 32*64; l += 256) {
            int key = l >> 6, c = l & 63;
            Vs[key][c] = v[base + (size_t)(k0 + key) * D_ + c];
        }
        __syncthreads();

        // S tile: 64 queries x 32 keys, contraction over HD=64
        float s[4][2] = {};
        #pragma unroll 8
        for (int kk = 0; kk < 64; kk++) {
            float a0 = Qs[r0    ][kk];
            float a1 = Qs[r0 + 1][kk];
            float a2 = Qs[r0 + 2][kk];
            float a3 = Qs[r0 + 3][kk];
            float b0 = Kts[kk][cS];
            float b1 = Kts[kk][cS + 1];
            s[0][0] = fmaf(a0, b0, s[0][0]); s[0][1] = fmaf(a0, b1, s[0][1]);
            s[1][0] = fmaf(a1, b0, s[1][0]); s[1][1] = fmaf(a1, b1, s[1][1]);
            s[2][0] = fmaf(a2, b0, s[2][0]); s[2][1] = fmaf(a2, b1, s[2][1]);
            s[3][0] = fmaf(a3, b0, s[3][0]); s[3][1] = fmaf(a3, b1, s[3][1]);
        }
        #pragma unroll
        for (int i = 0; i < 4; i++) {
            Ss[r0 + i][cS    ] = fmaxf(s[i][0] * 0.125f, 0.f);
            Ss[r0 + i][cS + 1] = fmaxf(s[i][1] * 0.125f, 0.f);
        }
        __syncthreads();

        if (tid < 64) {
            float d = 0.f;
            #pragma unroll 8
            for (int j = 0; j < 32; j++) d += Ss[tid][j];
            denom[tid] += d;
        }

        // acc += P @ V : 64x64 accumulator, contraction over 32 keys
        #pragma unroll 4
        for (int kk = 0; kk < 32; kk++) {
            float a[4], b[4];
            #pragma unroll
            for (int i = 0; i < 4; i++) a[i] = Ss[r0 + i][kk];
            #pragma unroll
            for (int j = 0; j < 4; j++) b[j] = Vs[kk][cA + j];
            #pragma unroll
            for (int i = 0; i < 4; i++)
                #pragma unroll
                for (int j = 0; j < 4; j++)
                    acc[i][j] = fmaf(a[i], b[j], acc[i][j]);
        }
        __syncthreads();
    }

    #pragma unroll
    for (int i = 0; i < 4; i++) {
        float inv = 1.f / (denom[r0 + i] + 1e-6f);
        #pragma unroll
        for (int j = 0; j < 4; j++)
            ctx[base + (size_t)(q0 + r0 + i) * D_ + cA + j] = acc[i][j] * inv;
    }
}

// ---------------------------------------------------------------------------
// Launcher. Input order (metadata): x, wq, bq, wk, bk, wv, bv, wo, bo
// ---------------------------------------------------------------------------
extern "C" void kernel_launch(void* const* d_in, const int* in_sizes, int n_in,
                              void* d_out, int out_size)
{
    const float* x  = (const float*)d_in[0];
    const float* wq = (const float*)d_in[1];
    const float* bq = (const float*)d_in[2];
    const float* wk = (const float*)d_in[3];
    const float* bk = (const float*)d_in[4];
    const float* wv = (const float*)d_in[5];
    const float* bv = (const float*)d_in[6];
    const float* wo = (const float*)d_in[7];
    const float* bo = (const float*)d_in[8];
    float* out = (float*)d_out;

    float *q, *k, *v, *ctx;
    cudaGetSymbolAddress((void**)&q,   g_q);
    cudaGetSymbolAddress((void**)&k,   g_k);
    cudaGetSymbolAddress((void**)&v,   g_v);
    cudaGetSymbolAddress((void**)&ctx, g_ctx);

    dim3 blk(256);
    dim3 gProj(D_ / 64, M_ / 64);          // 8 x 256
    gemm_bias_kernel<<<gProj, blk>>>(x, wq, bq, q, M_, D_, D_);
    gemm_bias_kernel<<<gProj, blk>>>(x, wk, bk, k, M_, D_, D_);
    gemm_bias_kernel<<<gProj, blk>>>(x, wv, bv, v, M_, D_, D_);

    dim3 gAttn(N_ / 64, T_ * B_ * H_);     // 16 x 128
    attn_kernel<<<gAttn, blk>>>(q, k, v, ctx);

    gemm_bias_kernel<<<gProj, blk>>>(ctx, wo, bo, out, M_, D_, D_);
}

// round 2
// speedup vs baseline: 1.3879x; 1.3879x over previous
#include <cuda_runtime.h>
#include <cstdint>

// Problem constants
#define T_  4
#define B_  4
#define N_  1024
#define D_  512
#define H_  8
#define HD_ 64
#define M_  (T_*B_*N_)   // 16384 rows

// Scratch (no cudaMalloc allowed)
__device__ float g_q  [(size_t)M_*D_];
__device__ float g_k  [(size_t)M_*D_];
__device__ float g_v  [(size_t)M_*D_];
__device__ float g_ctx[(size_t)M_*D_];

// ---------------------------------------------------------------------------
// TF32 helpers
// ---------------------------------------------------------------------------
__device__ __forceinline__ uint32_t f2tf32(float x) {
    uint32_t y;
    asm("cvt.rna.tf32.f32 %0, %1;" : "=r"(y) : "f"(x));
    return y;
}
__device__ __forceinline__ void split_tf32(float x, uint32_t& hi, uint32_t& lo) {
    hi = f2tf32(x);
    float r = x - __uint_as_float(hi);
    lo = f2tf32(r);
}
__device__ __forceinline__ void mma_tf32(float c[4], const uint32_t a[4],
                                         uint32_t b0, uint32_t b1) {
    asm volatile(
        "mma.sync.aligned.m16n8k8.row.col.f32.tf32.tf32.f32 "
        "{%0,%1,%2,%3}, {%4,%5,%6,%7}, {%8,%9}, {%0,%1,%2,%3};"
        : "+f"(c[0]), "+f"(c[1]), "+f"(c[2]), "+f"(c[3])
        : "r"(a[0]), "r"(a[1]), "r"(a[2]), "r"(a[3]), "r"(b0), "r"(b1));
}

// ---------------------------------------------------------------------------
// Tensor-core GEMM: C[M,Nc] = A[M,K] @ W[Nc,K]^T + bias  (3xTF32 split)
// Block tile 128x128, 256 threads = 8 warps (4 along M x 2 along N),
// warp tile 32x64. K-chunk 32 (4 x k8 steps).
// ---------------------------------------------------------------------------
__global__ __launch_bounds__(256) void gemm_mma_kernel(
    const float* __restrict__ A, const float* __restrict__ W,
    const float* __restrict__ bias, float* __restrict__ C,
    int M, int Nc, int K)
{
    __shared__ float As[128][36];   // [m][k], 36 pad keeps 16B alignment
    __shared__ float Ws[128][36];   // [n][k]

    const int tid  = threadIdx.x;
    const int lane = tid & 31, warp = tid >> 5;
    const int g    = lane >> 2, tg = lane & 3;
    const int wm   = (warp >> 1) * 32;   // warp M offset within block
    const int wn   = (warp & 1) * 64;    // warp N offset within block
    const int mb   = blockIdx.y * 128, nb = blockIdx.x * 128;

    float acc[2][8][4];
    #pragma unroll
    for (int i = 0; i < 2; i++)
        #pragma unroll
        for (int j = 0; j < 8; j++)
            #pragma unroll
            for (int l = 0; l < 4; l++) acc[i][j][l] = 0.f;

    for (int kb = 0; kb < K; kb += 32) {
        // load A tile 128x32 and W tile 128x32 via float4 (4 per thread each)
        #pragma unroll
        for (int l = tid; l < 1024; l += 256) {
            int r = l >> 3, c4 = (l & 7) * 4;
            *(float4*)&As[r][c4] = *(const float4*)&A[(size_t)(mb + r) * K + kb + c4];
        }
        #pragma unroll
        for (int l = tid; l < 1024; l += 256) {
            int r = l >> 3, c4 = (l & 7) * 4;
            *(float4*)&Ws[r][c4] = *(const float4*)&W[(size_t)(nb + r) * K + kb + c4];
        }
        __syncthreads();

        #pragma unroll
        for (int k8 = 0; k8 < 32; k8 += 8) {
            // A fragments for the warp's two 16-row subtiles
            uint32_t ahi[2][4], alo[2][4];
            #pragma unroll
            for (int mi = 0; mi < 2; mi++) {
                int m = wm + mi * 16;
                float a0 = As[m + g    ][k8 + tg    ];
                float a1 = As[m + g + 8][k8 + tg    ];
                float a2 = As[m + g    ][k8 + tg + 4];
                float a3 = As[m + g + 8][k8 + tg + 4];
                split_tf32(a0, ahi[mi][0], alo[mi][0]);
                split_tf32(a1, ahi[mi][1], alo[mi][1]);
                split_tf32(a2, ahi[mi][2], alo[mi][2]);
                split_tf32(a3, ahi[mi][3], alo[mi][3]);
            }
            #pragma unroll
            for (int nj = 0; nj < 8; nj++) {
                int n = wn + nj * 8;
                float b0f = Ws[n + g][k8 + tg    ];
                float b1f = Ws[n + g][k8 + tg + 4];
                uint32_t bh0, bl0, bh1, bl1;
                split_tf32(b0f, bh0, bl0);
                split_tf32(b1f, bh1, bl1);
                #pragma unroll
                for (int mi = 0; mi < 2; mi++) {
                    mma_tf32(acc[mi][nj], ahi[mi], bh0, bh1);  // hi*hi
                    mma_tf32(acc[mi][nj], ahi[mi], bl0, bl1);  // hi*lo
                    mma_tf32(acc[mi][nj], alo[mi], bh0, bh1);  // lo*hi
                }
            }
        }
        __syncthreads();
    }

    // Epilogue: c0:(g,2tg) c1:(g,2tg+1) c2:(g+8,2tg) c3:(g+8,2tg+1)
    #pragma unroll
    for (int mi = 0; mi < 2; mi++) {
        int r0 = mb + wm + mi * 16 + g;
        #pragma unroll
        for (int nj = 0; nj < 8; nj++) {
            int c0 = nb + wn + nj * 8 + 2 * tg;
            float bia0 = bias[c0], bia1 = bias[c0 + 1];
            C[(size_t)r0 * Nc + c0    ]       = acc[mi][nj][0] + bia0;
            C[(size_t)r0 * Nc + c0 + 1]       = acc[mi][nj][1] + bia1;
            C[(size_t)(r0 + 8) * Nc + c0    ] = acc[mi][nj][2] + bia0;
            C[(size_t)(r0 + 8) * Nc + c0 + 1] = acc[mi][nj][3] + bia1;
        }
    }
}

// ---------------------------------------------------------------------------
// ReLU-normalized attention (unchanged from round 1)
// ---------------------------------------------------------------------------
__global__ __launch_bounds__(256) void attn_kernel(
    const float* __restrict__ q, const float* __restrict__ k,
    const float* __restrict__ v, float* __restrict__ ctx)
{
    __shared__ float Qs [64][65];
    __shared__ float Kts[64][33];
    __shared__ float Vs [32][65];
    __shared__ float Ss [64][33];
    __shared__ float denom[64];

    const int tid = threadIdx.x;
    const int hi  = blockIdx.y;
    const int h   = hi & (H_ - 1);
    const int tb  = hi >> 3;
    const size_t base = (size_t)tb * N_ * D_ + (size_t)h * HD_;
    const int q0  = blockIdx.x * 64;

    const int ty = tid >> 4, tx = tid & 15;
    const int r0 = ty * 4;
    const int cS = tx * 2;
    const int cA = tx * 4;

    for (int l = tid; l < 64*64; l += 256) {
        int r = l >> 6, c = l & 63;
        Qs[r][c] = q[base + (size_t)(q0 + r) * D_ + c];
    }
    if (tid < 64) denom[tid] = 0.f;
    float acc[4][4] = {};
    __syncthreads();

    for (int k0 = 0; k0 < N_; k0 += 32) {
        for (int l = tid; l < 32*64; l += 256) {
            int key = l >> 6, c = l & 63;
            Kts[c][key] = k[base + (size_t)(k0 + key) * D_ + c];
        }
        for (int l = tid; l < 32*64; l += 256) {
            int key = l >> 6, c = l & 63;
            Vs[key][c] = v[base + (size_t)(k0 + key) * D_ + c];
        }
        __syncthreads();

        float s[4][2] = {};
        #pragma unroll 8
        for (int kk = 0; kk < 64; kk++) {
            float a0 = Qs[r0    ][kk];
            float a1 = Qs[r0 + 1][kk];
            float a2 = Qs[r0 + 2][kk];
            float a3 = Qs[r0 + 3][kk];
            float b0 = Kts[kk][cS];
            float b1 = Kts[kk][cS + 1];
            s[0][0] = fmaf(a0, b0, s[0][0]); s[0][1] = fmaf(a0, b1, s[0][1]);
            s[1][0] = fmaf(a1, b0, s[1][0]); s[1][1] = fmaf(a1, b1, s[1][1]);
            s[2][0] = fmaf(a2, b0, s[2][0]); s[2][1] = fmaf(a2, b1, s[2][1]);
            s[3][0] = fmaf(a3, b0, s[3][0]); s[3][1] = fmaf(a3, b1, s[3][1]);
        }
        #pragma unroll
        for (int i = 0; i < 4; i++) {
            Ss[r0 + i][cS    ] = fmaxf(s[i][0] * 0.125f, 0.f);
            Ss[r0 + i][cS + 1] = fmaxf(s[i][1] * 0.125f, 0.f);
        }
        __syncthreads();

        if (tid < 64) {
            float d = 0.f;
            #pragma unroll 8
            for (int j = 0; j < 32; j++) d += Ss[tid][j];
            denom[tid] += d;
        }

        #pragma unroll 4
        for (int kk = 0; kk < 32; kk++) {
            float a[4], b[4];
            #pragma unroll
            for (int i = 0; i < 4; i++) a[i] = Ss[r0 + i][kk];
            #pragma unroll
            for (int j = 0; j < 4; j++) b[j] = Vs[kk][cA + j];
            #pragma unroll
            for (int i = 0; i < 4; i++)
                #pragma unroll
                for (int j = 0; j < 4; j++)
                    acc[i][j] = fmaf(a[i], b[j], acc[i][j]);
        }
        __syncthreads();
    }

    #pragma unroll
    for (int i = 0; i < 4; i++) {
        float inv = 1.f / (denom[r0 + i] + 1e-6f);
        #pragma unroll
        for (int j = 0; j < 4; j++)
            ctx[base + (size_t)(q0 + r0 + i) * D_ + cA + j] = acc[i][j] * inv;
    }
}

// ---------------------------------------------------------------------------
// Launcher. Input order: x, wq, bq, wk, bk, wv, bv, wo, bo
// ---------------------------------------------------------------------------
extern "C" void kernel_launch(void* const* d_in, const int* in_sizes, int n_in,
                              void* d_out, int out_size)
{
    const float* x  = (const float*)d_in[0];
    const float* wq = (const float*)d_in[1];
    const float* bq = (const float*)d_in[2];
    const float* wk = (const float*)d_in[3];
    const float* bk = (const float*)d_in[4];
    const float* wv = (const float*)d_in[5];
    const float* bv = (const float*)d_in[6];
    const float* wo = (const float*)d_in[7];
    const float* bo = (const float*)d_in[8];
    float* out = (float*)d_out;

    float *q, *k, *v, *ctx;
    cudaGetSymbolAddress((void**)&q,   g_q);
    cudaGetSymbolAddress((void**)&k,   g_k);
    cudaGetSymbolAddress((void**)&v,   g_v);
    cudaGetSymbolAddress((void**)&ctx, g_ctx);

    dim3 blk(256);
    dim3 gProj(D_ / 128, M_ / 128);        // 4 x 128
    gemm_mma_kernel<<<gProj, blk>>>(x, wq, bq, q, M_, D_, D_);
    gemm_mma_kernel<<<gProj, blk>>>(x, wk, bk, k, M_, D_, D_);
    gemm_mma_kernel<<<gProj, blk>>>(x, wv, bv, v, M_, D_, D_);

    dim3 gAttn(N_ / 64, T_ * B_ * H_);     // 16 x 128
    attn_kernel<<<gAttn, blk>>>(q, k, v, ctx);

    gemm_mma_kernel<<<gProj, blk>>>(ctx, wo, bo, out, M_, D_, D_);
}